// round 2
// baseline (speedup 1.0000x reference)
#include <cuda_runtime.h>
#include <math.h>

#define BS   8
#define HW   1024
#define STEP 20
#define NS   51          // hw // STEP
#define NP   512         // model points
#define NBLK (BS * NS)   // 408 hypotheses
#define SCORING_WEIGHT 0.01f

// Scratch (no allocations allowed): GT points packed as (-2gx,-2gy,-2gz,gn)
__device__ float4 g_gt[BS][NP];
__device__ float  g_part[NBLK];

// ---------------------------------------------------------------------------
// Kernel A: per-batch GT point cloud: g = gt_r @ model + gt_t, pack for the
// min-distance inner loop.
// ---------------------------------------------------------------------------
__global__ void gt_kernel(const float* __restrict__ gt_r,
                          const float* __restrict__ gt_t,
                          const float* __restrict__ model)
{
    int b = blockIdx.x;
    int p = threadIdx.x;
    const float* R = gt_r + b * 9;
    const float* t = gt_t + b * 3;
    const float* m = model + b * 3 * NP;

    float mx = m[p], my = m[NP + p], mz = m[2 * NP + p];
    float gx = fmaf(R[0], mx, fmaf(R[1], my, fmaf(R[2], mz, t[0])));
    float gy = fmaf(R[3], mx, fmaf(R[4], my, fmaf(R[5], mz, t[1])));
    float gz = fmaf(R[6], mx, fmaf(R[7], my, fmaf(R[8], mz, t[2])));
    float gn = fmaf(gx, gx, fmaf(gy, gy, gz * gz));
    g_gt[b][p] = make_float4(-2.0f * gx, -2.0f * gy, -2.0f * gz, gn);
}

// ---------------------------------------------------------------------------
// Kernel B: one block per (batch, sample). 512 threads, one model point each.
// Inner loop over 512 GT points is a shared-memory broadcast: 1 LDS.128 +
// 3 FFMA + 1 FMNMX per candidate.
// ---------------------------------------------------------------------------
__global__ __launch_bounds__(NP) void add_kernel(const float* __restrict__ pred_r,
                                                 const float* __restrict__ pred_t,
                                                 const float* __restrict__ pred_s,
                                                 const float* __restrict__ model)
{
    __shared__ float4 sg[NP];
    __shared__ float  red[NP];

    int blk = blockIdx.x;
    int b   = blk / NS;
    int n   = blk % NS;
    int pix = n * STEP;
    int tid = threadIdx.x;

    sg[tid] = g_gt[b][tid];

    // ---- pose from predictions (tiny, every thread redundantly) ----
    const float* pr = pred_r + b * 4 * HW + pix;
    float q0 = pr[0], q1 = pr[HW], q2 = pr[2 * HW], q3 = pr[3 * HW];
    float inv = rsqrtf(q0 * q0 + q1 * q1 + q2 * q2 + q3 * q3);
    q0 *= inv; q1 *= inv; q2 *= inv; q3 *= inv;

    float R00 = 1.0f - 2.0f * (q2 * q2 + q3 * q3);
    float R01 = 2.0f * (q1 * q2 - q0 * q3);
    float R02 = 2.0f * (q0 * q2 + q1 * q3);
    float R10 = 2.0f * (q1 * q2 + q3 * q0);
    float R11 = 1.0f - 2.0f * (q1 * q1 + q3 * q3);
    float R12 = 2.0f * (q2 * q3 - q0 * q1);
    float R20 = 2.0f * (q1 * q3 - q0 * q2);
    float R21 = 2.0f * (q0 * q1 + q2 * q3);
    float R22 = 1.0f - 2.0f * (q1 * q1 + q2 * q2);

    const float* pt = pred_t + b * 3 * HW + pix;
    float tx = pt[0], ty = pt[HW], tz = pt[2 * HW];

    const float* m = model + b * 3 * NP;
    float mx = m[tid], my = m[NP + tid], mz = m[2 * NP + tid];

    float px = fmaf(R00, mx, fmaf(R01, my, fmaf(R02, mz, tx)));
    float py = fmaf(R10, mx, fmaf(R11, my, fmaf(R12, mz, ty)));
    float pz = fmaf(R20, mx, fmaf(R21, my, fmaf(R22, mz, tz)));
    float pn = fmaf(px, px, fmaf(py, py, pz * pz));

    __syncthreads();

    // ---- nearest-neighbor: min_q (gn - 2 p.g) ----
    float mn = 3.0e38f;
#pragma unroll 8
    for (int q = 0; q < NP; q++) {
        float4 g = sg[q];
        float v = fmaf(px, g.x, fmaf(py, g.y, fmaf(pz, g.z, g.w)));
        mn = fminf(mn, v);
    }
    float dmin = sqrtf(fmaxf(pn + mn, 0.0f));

    // ---- block reduction: sum of dmin over the 512 model points ----
    red[tid] = dmin;
    __syncthreads();
#pragma unroll
    for (int s = NP / 2; s >= 32; s >>= 1) {   // fold down to 32 INCLUSIVE
        if (tid < s) red[tid] += red[tid + s];
        __syncthreads();
    }
    if (tid < 32) {
        float v = red[tid];                     // red[0..31] already hold full sums
#pragma unroll
        for (int o = 16; o > 0; o >>= 1)
            v += __shfl_down_sync(0xFFFFFFFFu, v, o);
        if (tid == 0) {
            float add = v * (1.0f / NP);
            float s_  = pred_s[b * HW + pix];
            g_part[blk] = (add * s_ - SCORING_WEIGHT * logf(s_)) * (1.0f / NBLK);
        }
    }
}

// ---------------------------------------------------------------------------
// Kernel C: deterministic reduction of the 408 partials + inf/nan guard.
// ---------------------------------------------------------------------------
__global__ void finish_kernel(float* __restrict__ out)
{
    __shared__ float red[512];
    int tid = threadIdx.x;
    red[tid] = (tid < NBLK) ? g_part[tid] : 0.0f;
    __syncthreads();
#pragma unroll
    for (int s = 256; s > 0; s >>= 1) {
        if (tid < s) red[tid] += red[tid + s];
        __syncthreads();
    }
    if (tid == 0) {
        float r = red[0];
        if (isinf(r) || isnan(r)) r = 0.0f;
        out[0] = r;
    }
}

// ---------------------------------------------------------------------------
// Inputs (metadata order): pred_r, pred_t, pred_s, mask, gt_r, gt_t,
//                          model_xyz, cls_ids
// ---------------------------------------------------------------------------
extern "C" void kernel_launch(void* const* d_in, const int* in_sizes, int n_in,
                              void* d_out, int out_size)
{
    const float* pred_r = (const float*)d_in[0];
    const float* pred_t = (const float*)d_in[1];
    const float* pred_s = (const float*)d_in[2];
    // d_in[3] = mask (unused)
    const float* gt_r   = (const float*)d_in[4];
    const float* gt_t   = (const float*)d_in[5];
    const float* model  = (const float*)d_in[6];
    // d_in[7] = cls_ids (unused)

    gt_kernel<<<BS, NP>>>(gt_r, gt_t, model);
    add_kernel<<<NBLK, NP>>>(pred_r, pred_t, pred_s, model);
    finish_kernel<<<1, 512>>>((float*)d_out);
}